// round 13
// baseline (speedup 1.0000x reference)
#include <cuda_runtime.h>
#include <cuda_fp16.h>
#include <cstdint>

// N=32768, D=128, K=1024. scores = ||c||^2 - 2 x.c
// Phase A: approx via single fp16 HMMA (xh*ch, fp32 acc). 8 warps, 32x64 warp
//   tiles, A fragments register-resident for the whole mainloop.
//   Fold per (lane,slot): sm1 + exact code idx i1, uu = rigorous lower bound
//   on untracked codes.
// Phase B: provable window rescue. Single-code items: PER-THREAD parallel
//   exact fp32 rescore (dense queue -> all lanes active). Rare slot fallback:
//   warp-level. Packed u64 atomicMin (ties -> lowest index).

#define DDIM     128
#define KCODES   1024
#define MT       128
#define NTILE    128
#define NT_CNT   (KCODES / NTILE)   // 8
#define NTHREADS 256
#define QS_CAP   2048
#define QF_CAP   512

__device__ __half   g_cbh[KCODES * DDIM];
__device__ float    g_cnorm[KCODES];
__device__ unsigned g_maxcl_bits = 0;
__device__ unsigned g_maxch_bits = 0;

// ---------------- SMEM layout (bytes) ----------------
#define SM_AH    0         // xh tile, swizzled fp16: 32KB
#define SM_B     32768     // B ring: 3 x 32KB = 96KB
#define SM_X     131072    // x tile fp32: 64KB
#define SM_RMIN  196608    // rowmin u32 [128]
#define SM_WROW  197120    // W_row float [128]
#define SM_RBEST 197632    // rowbest u64 [128]
#define SM_QN    198656    // counts: qs, qf
#define SM_QS    198784    // u32 [QS_CAP] = 8KB
#define SM_QF    206976    // u32 [QF_CAP] = 2KB
#define SMEM_BYTES 209024

__device__ __forceinline__ uint32_t smem_u32(const void* p) {
    uint32_t a;
    asm("{ .reg .u64 t; cvta.to.shared.u64 t, %1; cvt.u32.u64 %0, t; }" : "=r"(a) : "l"(p));
    return a;
}
__device__ __forceinline__ void cp_async16(uint32_t dst, const void* src) {
    asm volatile("cp.async.cg.shared.global [%0], [%1], 16;" :: "r"(dst), "l"(src) : "memory");
}
__device__ __forceinline__ void cp_commit() {
    asm volatile("cp.async.commit_group;" ::: "memory");
}
template <int W>
__device__ __forceinline__ void cp_wait() {
    asm volatile("cp.async.wait_group %0;" :: "n"(W) : "memory");
}
__device__ __forceinline__ void ldsm4(uint32_t& r0, uint32_t& r1, uint32_t& r2, uint32_t& r3,
                                      uint32_t addr) {
    asm volatile("ldmatrix.sync.aligned.m8n8.x4.shared.b16 {%0,%1,%2,%3}, [%4];"
                 : "=r"(r0), "=r"(r1), "=r"(r2), "=r"(r3) : "r"(addr));
}
__device__ __forceinline__ void mma_f32(float* c, const uint32_t* a, uint32_t b0, uint32_t b1) {
    asm volatile(
        "mma.sync.aligned.m16n8k16.row.col.f32.f16.f16.f32 "
        "{%0,%1,%2,%3}, {%4,%5,%6,%7}, {%8,%9}, {%0,%1,%2,%3};"
        : "+f"(c[0]), "+f"(c[1]), "+f"(c[2]), "+f"(c[3])
        : "r"(a[0]), "r"(a[1]), "r"(a[2]), "r"(a[3]), "r"(b0), "r"(b1));
}
__device__ __forceinline__ uint32_t fp_order(float f) {
    uint32_t u = __float_as_uint(f);
    return u ^ ((u >> 31) ? 0xFFFFFFFFu : 0x80000000u);
}
__device__ __forceinline__ float fp_unorder(uint32_t e) {
    uint32_t u = (e >> 31) ? (e ^ 0x80000000u) : ~e;
    return __uint_as_float(u);
}

// ---------------- prep: fp16 codebook, norms, error-bound norms ----------------
__global__ void prep_kernel(const float* __restrict__ cb) {
    int k = blockIdx.x, d = threadIdx.x;
    float v = cb[k * DDIM + d];
    __half h = __float2half_rn(v);
    g_cbh[k * DDIM + d] = h;
    float hf = __half2float(h);
    float cl = v - hf;
    float s = v * v, s2 = cl * cl, s3 = hf * hf;
#pragma unroll
    for (int o = 16; o; o >>= 1) {
        s  += __shfl_xor_sync(~0u, s,  o);
        s2 += __shfl_xor_sync(~0u, s2, o);
        s3 += __shfl_xor_sync(~0u, s3, o);
    }
    __shared__ float ws[4][3];
    if ((threadIdx.x & 31) == 0) {
        int w = threadIdx.x >> 5;
        ws[w][0] = s; ws[w][1] = s2; ws[w][2] = s3;
    }
    __syncthreads();
    if (threadIdx.x == 0) {
        g_cnorm[k] = ws[0][0] + ws[1][0] + ws[2][0] + ws[3][0];
        float ncl = sqrtf(ws[0][1] + ws[1][1] + ws[2][1] + ws[3][1]);
        float nch = sqrtf(ws[0][2] + ws[1][2] + ws[2][2] + ws[3][2]);
        atomicMax(&g_maxcl_bits, __float_as_uint(ncl));
        atomicMax(&g_maxch_bits, __float_as_uint(nch));
    }
}

extern __shared__ char smem[];

__device__ __forceinline__ void issue_b_tile(uint32_t sb, int nt, int st, int tid) {
#pragma unroll
    for (int i = 0; i < 8; i++) {
        int ch  = i * NTHREADS + tid;          // 2048 chunks of 16B
        int row = ch >> 4;
        int c16 = ch & 15;
        const __half* src = g_cbh + ((size_t)(nt * NTILE + row) * DDIM + c16 * 8);
        uint32_t dst = sb + SM_B + (uint32_t)st * 32768u
                     + (uint32_t)(row * 16 + (c16 ^ (row & 7))) * 16u;
        cp_async16(dst, src);
    }
    cp_commit();
}

__global__ __launch_bounds__(NTHREADS, 1) void vq_mma_kernel(
    const float* __restrict__ x, const float* __restrict__ cb, float* __restrict__ out)
{
    const uint32_t sb = smem_u32(smem);
    const int tid  = threadIdx.x;
    const int lane = tid & 31;
    const int warp = tid >> 5;       // 0..7
    const int wm   = warp >> 1;      // 0..3 : rows wm*32..+31
    const int wn   = warp & 1;       // 0..1 : cols wn*64..+63
    const int m0   = blockIdx.x * MT;

    unsigned*           rowmin  = reinterpret_cast<unsigned*>(smem + SM_RMIN);
    float*              wrow    = reinterpret_cast<float*>(smem + SM_WROW);
    unsigned long long* rowbest = reinterpret_cast<unsigned long long*>(smem + SM_RBEST);
    unsigned*           qn      = reinterpret_cast<unsigned*>(smem + SM_QN);
    unsigned*           qs      = reinterpret_cast<unsigned*>(smem + SM_QS);
    unsigned*           qf      = reinterpret_cast<unsigned*>(smem + SM_QF);

    issue_b_tile(sb, 0, 0, tid);
    issue_b_tile(sb, 1, 1, tid);

    const int t8 = lane >> 3;
    const int j8 = lane & 7;

    // ---- prologue: x -> SM_X, convert hi -> AH, row norms + windows ----
    {
        const float4* xsrc = reinterpret_cast<const float4*>(x + (size_t)m0 * DDIM);
        float4* xs4 = reinterpret_cast<float4*>(smem + SM_X);
#pragma unroll
        for (int i = 0; i < 16; i++) xs4[i * NTHREADS + tid] = xsrc[i * NTHREADS + tid];
        __syncthreads();
        const float* xs = reinterpret_cast<const float*>(smem + SM_X);
#pragma unroll
        for (int i = 0; i < 8; i++) {
            int oc  = i * NTHREADS + tid;      // 2048 fp16 chunks (16B)
            int row = oc >> 4;
            int hc  = oc & 15;
            const float* p = xs + row * DDIM + hc * 8;
            uint32_t hi[4];
#pragma unroll
            for (int j = 0; j < 4; j++) {
                __half h0 = __float2half_rn(p[j * 2]);
                __half h1 = __float2half_rn(p[j * 2 + 1]);
                hi[j] = ((uint32_t)__half_as_ushort(h1) << 16) | __half_as_ushort(h0);
            }
            uint32_t chunk = (uint32_t)(row * 16 + (hc ^ (row & 7))) * 16u;
            *reinterpret_cast<uint4*>(smem + SM_AH + chunk) = make_uint4(hi[0], hi[1], hi[2], hi[3]);
        }
        {   // per-row ||x||, ||x - fl16(x)|| -> rigorous window (2 threads/row)
            int row  = tid >> 1;
            int part = tid & 1;
            const float* p = xs + row * DDIM + part * 64;
            float s = 0.f, sl = 0.f;
#pragma unroll
            for (int q = 0; q < 64; q++) {
                float v  = p[q];
                float lv = v - __half2float(__float2half_rn(v));
                s  = fmaf(v, v, s);
                sl = fmaf(lv, lv, sl);
            }
            s  += __shfl_xor_sync(~0u, s, 1);
            sl += __shfl_xor_sync(~0u, sl, 1);
            if (part == 0) {
                float mcl = __uint_as_float(g_maxcl_bits);
                float mch = __uint_as_float(g_maxch_bits);
                float nx = sqrtf(s), nxl = sqrtf(sl);
                wrow[row] = 4.f * ((nx + nxl) * mcl + nxl * (mch + mcl)) + 2e-3f;
            }
        }
        if (tid < MT) { rowmin[tid] = 0xFFFFFFFFu; rowbest[tid] = ~0ull; }
        if (tid == 0) { qn[0] = 0; qn[1] = 0; }
        __syncthreads();
    }

    // ---- load A fragments once, register-resident for the whole mainloop ----
    uint32_t ahr[8][2][4];
#pragma unroll
    for (int kc = 0; kc < 8; kc++) {
        const int c16 = kc * 2 + (t8 >> 1);
#pragma unroll
        for (int mi = 0; mi < 2; mi++) {
            int row = wm * 32 + mi * 16 + (t8 & 1) * 8 + j8;
            uint32_t off = (uint32_t)(row * 16 + (c16 ^ (row & 7))) * 16u;
            ldsm4(ahr[kc][mi][0], ahr[kc][mi][1], ahr[kc][mi][2], ahr[kc][mi][3],
                  sb + SM_AH + off);
        }
    }

    // per-slot (mi*2+h): best score + exact idx, uu bound on untracked
    float sm1[4], uu[4];
    int   i1[4];
#pragma unroll
    for (int s = 0; s < 4; s++) { sm1[s] = 3.4e38f; uu[s] = 3.4e38f; i1[s] = 0; }

    for (int nt = 0; nt < NT_CNT; nt++) {
        if (nt + 1 < NT_CNT) cp_wait<1>(); else cp_wait<0>();
        __syncthreads();
        if (nt + 2 < NT_CNT) issue_b_tile(sb, nt + 2, (nt + 2) % 3, tid);

        const uint32_t bhb = sb + SM_B + (uint32_t)(nt % 3) * 32768u;

        float acc[2][8][4];
#pragma unroll
        for (int mi = 0; mi < 2; mi++)
#pragma unroll
            for (int ni = 0; ni < 8; ni++)
#pragma unroll
                for (int c = 0; c < 4; c++) acc[mi][ni][c] = 0.f;

#pragma unroll
        for (int kc = 0; kc < 8; kc++) {
            const int c16 = kc * 2 + (t8 >> 1);
            uint32_t bh[4][4];
#pragma unroll
            for (int bi = 0; bi < 4; bi++) {
                int nrow = wn * 64 + bi * 16 + (t8 & 1) * 8 + j8;
                uint32_t off = (uint32_t)(nrow * 16 + (c16 ^ (nrow & 7))) * 16u;
                ldsm4(bh[bi][0], bh[bi][1], bh[bi][2], bh[bi][3], bhb + off);
            }
#pragma unroll
            for (int mi = 0; mi < 2; mi++)
#pragma unroll
                for (int ni = 0; ni < 8; ni++) {
                    int bi = ni >> 1, sub = ni & 1;
                    mma_f32(acc[mi][ni], ahr[kc][mi], bh[bi][sub], bh[bi][sub + 2]);
                }
        }

        // ---- fold: per slot 16 scores; track (sm1,i1) exact + uu bound ----
        const int base = nt * NTILE + wn * 64 + 2 * (lane & 3);
#pragma unroll
        for (int mi = 0; mi < 2; mi++)
#pragma unroll
            for (int h = 0; h < 2; h++) {
                const int s = mi * 2 + h;
                float sc[16];
#pragma unroll
                for (int ni = 0; ni < 8; ni++) {
                    int col0 = base + ni * 8;
                    sc[ni * 2]     = fmaf(-2.f, acc[mi][ni][2 * h],     __ldg(&g_cnorm[col0]));
                    sc[ni * 2 + 1] = fmaf(-2.f, acc[mi][ni][2 * h + 1], __ldg(&g_cnorm[col0 + 1]));
                }
                float m = sc[0];
#pragma unroll
                for (int j = 1; j < 16; j++) m = fminf(m, sc[j]);
                if (m < sm1[s]) {
                    int jm = 15;
#pragma unroll
                    for (int j = 15; j >= 0; j--) if (sc[j] == m) jm = j;
                    float t2 = 3.4e38f;
#pragma unroll
                    for (int j = 0; j < 16; j++) t2 = (j == jm) ? t2 : fminf(t2, sc[j]);
                    uu[s] = fminf(uu[s], fminf(sm1[s], t2));
                    sm1[s] = m;
                    i1[s] = base + (jm >> 1) * 8 + (jm & 1);
                } else {
                    uu[s] = fminf(uu[s], m);
                }
            }
    }

    // ---- row approx min ----
#pragma unroll
    for (int s = 0; s < 4; s++) {
        int row = wm * 32 + (s >> 1) * 16 + (s & 1) * 8 + (lane >> 2);
        atomicMin(&rowmin[row], fp_order(sm1[s]));
    }
    __syncthreads();

    // ---- push candidates ----
    const int cbase = wn * 64 + 2 * (lane & 3);
#pragma unroll
    for (int s = 0; s < 4; s++) {
        int row = wm * 32 + (s >> 1) * 16 + (s & 1) * 8 + (lane >> 2);
        float thr = fp_unorder(rowmin[row]) + wrow[row];
        if (sm1[s] <= thr) {
            unsigned slot = atomicAdd(&qn[0], 1u);
            if (slot < QS_CAP) qs[slot] = ((unsigned)row << 10) | (unsigned)i1[s];
        }
        if (uu[s] <= thr) {
            unsigned slot = atomicAdd(&qn[1], 1u);
            if (slot < QF_CAP) qf[slot] = ((unsigned)row << 7) | (unsigned)cbase;
        }
    }
    __syncthreads();

    const float* xsf = reinterpret_cast<const float*>(smem + SM_X);

    // ---- single-code rescue: PER-THREAD (dense queue, all lanes active) ----
    {
        int nqs = (int)min(qn[0], (unsigned)QS_CAP);
        for (int it = tid; it < nqs; it += NTHREADS) {
            unsigned item = qs[it];
            int row  = (int)(item >> 10);
            int code = (int)(item & 1023u);
            const float4* xr = reinterpret_cast<const float4*>(xsf + row * DDIM);
            const float4* cr = reinterpret_cast<const float4*>(cb + (size_t)code * DDIM);
            float d0 = 0.f, d1 = 0.f, d2 = 0.f, d3 = 0.f;
#pragma unroll
            for (int q = 0; q < 8; q++) {
                float4 a0 = xr[q * 4 + 0], b0 = __ldg(&cr[q * 4 + 0]);
                float4 a1 = xr[q * 4 + 1], b1 = __ldg(&cr[q * 4 + 1]);
                float4 a2 = xr[q * 4 + 2], b2 = __ldg(&cr[q * 4 + 2]);
                float4 a3 = xr[q * 4 + 3], b3 = __ldg(&cr[q * 4 + 3]);
                d0 = fmaf(a0.x, b0.x, d0); d0 = fmaf(a0.y, b0.y, d0);
                d0 = fmaf(a0.z, b0.z, d0); d0 = fmaf(a0.w, b0.w, d0);
                d1 = fmaf(a1.x, b1.x, d1); d1 = fmaf(a1.y, b1.y, d1);
                d1 = fmaf(a1.z, b1.z, d1); d1 = fmaf(a1.w, b1.w, d1);
                d2 = fmaf(a2.x, b2.x, d2); d2 = fmaf(a2.y, b2.y, d2);
                d2 = fmaf(a2.z, b2.z, d2); d2 = fmaf(a2.w, b2.w, d2);
                d3 = fmaf(a3.x, b3.x, d3); d3 = fmaf(a3.y, b3.y, d3);
                d3 = fmaf(a3.z, b3.z, d3); d3 = fmaf(a3.w, b3.w, d3);
            }
            float d = (d0 + d1) + (d2 + d3);
            float se = fmaf(-2.f, d, __ldg(&g_cnorm[code]));
            atomicMin(&rowbest[row],
                      ((unsigned long long)fp_order(se) << 32) | (uint32_t)code);
        }
    }

    // ---- slot fallback (rare): warp-level, 128 codes, 4 per lane ----
    {
        int nqf = (int)min(qn[1], (unsigned)QF_CAP);
        for (int it = warp; it < nqf; it += 8) {
            unsigned item = qf[it];
            int row = (int)(item >> 7);
            int cb0 = (int)(item & 127u);
            const float4* xr = reinterpret_cast<const float4*>(xsf + row * DDIM);
#pragma unroll
            for (int t = 0; t < 4; t++) {
                int e = lane + t * 32;                  // 0..127
                int nt2 = e >> 4, jj = e & 15;
                int code = nt2 * NTILE + cb0 + (jj >> 1) * 8 + (jj & 1);
                const float4* cr = reinterpret_cast<const float4*>(cb + (size_t)code * DDIM);
                float d0 = 0.f, d1 = 0.f;
#pragma unroll
                for (int q = 0; q < 16; q++) {
                    float4 a0 = xr[q * 2 + 0], b0 = __ldg(&cr[q * 2 + 0]);
                    float4 a1 = xr[q * 2 + 1], b1 = __ldg(&cr[q * 2 + 1]);
                    d0 = fmaf(a0.x, b0.x, d0); d0 = fmaf(a0.y, b0.y, d0);
                    d0 = fmaf(a0.z, b0.z, d0); d0 = fmaf(a0.w, b0.w, d0);
                    d1 = fmaf(a1.x, b1.x, d1); d1 = fmaf(a1.y, b1.y, d1);
                    d1 = fmaf(a1.z, b1.z, d1); d1 = fmaf(a1.w, b1.w, d1);
                }
                float se = fmaf(-2.f, d0 + d1, __ldg(&g_cnorm[code]));
                atomicMin(&rowbest[row],
                          ((unsigned long long)fp_order(se) << 32) | (uint32_t)code);
            }
        }
    }
    __syncthreads();

    // ---- output: out = x + (q - x), x from SMEM ----
    const float4* cb4 = reinterpret_cast<const float4*>(cb);
    const float4* xs4 = reinterpret_cast<const float4*>(smem + SM_X);
    float4* o4 = reinterpret_cast<float4*>(out);
#pragma unroll
    for (int i = 0; i < 16; i++) {
        int g  = i * NTHREADS + tid;           // 4096 float4
        int r  = g >> 5, c4 = g & 31;
        int bi = (int)(rowbest[r] & 0xFFFFFFFFu);
        float4 xv = xs4[r * 32 + c4];
        float4 qv = cb4[(size_t)bi * 32 + c4];
        float4 ov;
        ov.x = xv.x + (qv.x - xv.x);
        ov.y = xv.y + (qv.y - xv.y);
        ov.z = xv.z + (qv.z - xv.z);
        ov.w = xv.w + (qv.w - xv.w);
        o4[(size_t)(m0 + r) * 32 + c4] = ov;
    }
}

extern "C" void kernel_launch(void* const* d_in, const int* in_sizes, int n_in,
                              void* d_out, int out_size) {
    const float* x  = (const float*)d_in[0];
    const float* cb = (const float*)d_in[1];
    float* out = (float*)d_out;
    int N = in_sizes[0] / DDIM;     // 32768
    int K = in_sizes[1] / DDIM;     // 1024

    prep_kernel<<<K, DDIM>>>(cb);

    cudaFuncSetAttribute(vq_mma_kernel, cudaFuncAttributeMaxDynamicSharedMemorySize, SMEM_BYTES);
    vq_mma_kernel<<<N / MT, NTHREADS, SMEM_BYTES>>>(x, cb, out);
}

// round 15
// speedup vs baseline: 1.0388x; 1.0388x over previous
#include <cuda_runtime.h>
#include <cuda_fp16.h>
#include <cstdint>

// N=32768, D=128, K=1024. scores = ||c||^2 - 2 x.c
// Round 15 = round 11 with SW128 swizzle replaced by padded-row layout,
// CORRECT pitch this time: 128 fp16 = 256B data + 16B pad = 272B.
// ldmatrix conflict-free (row stride ≡ 4 banks mod 32), linear address math.
// Phase A: single fp16 HMMA (xh*ch, fp32 acc); fold tracks per-(lane,slot)
//   best score + exact code idx + uu lower bound on untracked codes.
// Phase B: provable window rescue (single-code warp-coop items + rare slot
//   fallback), exact fp32 rescore, packed u64 atomicMin (low-index ties).

#define DDIM     128
#define KCODES   1024
#define MT       128
#define NTILE    128
#define NT_CNT   (KCODES / NTILE)   // 8
#define NTHREADS 512
#define QCAP     4096
#define PITCH    272                // 256B row + 16B pad

__device__ __half   g_cbh[KCODES * DDIM];
__device__ float    g_cnorm[KCODES];
__device__ unsigned g_maxcl_bits = 0;
__device__ unsigned g_maxch_bits = 0;

// ---------------- SMEM layout (bytes) ----------------
#define AH_SZ    (128 * PITCH)          // 34816
#define B_SZ     (128 * PITCH)          // 34816 per stage
#define SM_AH    0
#define SM_B     34816                  // 3 stages -> ends 139264
#define SM_X     139264                 // x tile fp32 64KB -> ends 204800
#define SM_RMIN  204800
#define SM_WROW  205312
#define SM_RBEST 205824
#define SM_QN    206848
#define SM_QUEUE 206976
#define SMEM_BYTES (206976 + QCAP * 4)  // 223360

__device__ __forceinline__ uint32_t smem_u32(const void* p) {
    uint32_t a;
    asm("{ .reg .u64 t; cvta.to.shared.u64 t, %1; cvt.u32.u64 %0, t; }" : "=r"(a) : "l"(p));
    return a;
}
__device__ __forceinline__ void cp_async16(uint32_t dst, const void* src) {
    asm volatile("cp.async.cg.shared.global [%0], [%1], 16;" :: "r"(dst), "l"(src) : "memory");
}
__device__ __forceinline__ void cp_commit() {
    asm volatile("cp.async.commit_group;" ::: "memory");
}
template <int W>
__device__ __forceinline__ void cp_wait() {
    asm volatile("cp.async.wait_group %0;" :: "n"(W) : "memory");
}
__device__ __forceinline__ void ldsm4(uint32_t& r0, uint32_t& r1, uint32_t& r2, uint32_t& r3,
                                      uint32_t addr) {
    asm volatile("ldmatrix.sync.aligned.m8n8.x4.shared.b16 {%0,%1,%2,%3}, [%4];"
                 : "=r"(r0), "=r"(r1), "=r"(r2), "=r"(r3) : "r"(addr));
}
__device__ __forceinline__ void mma_f32(float* c, const uint32_t* a, uint32_t b0, uint32_t b1) {
    asm volatile(
        "mma.sync.aligned.m16n8k16.row.col.f32.f16.f16.f32 "
        "{%0,%1,%2,%3}, {%4,%5,%6,%7}, {%8,%9}, {%0,%1,%2,%3};"
        : "+f"(c[0]), "+f"(c[1]), "+f"(c[2]), "+f"(c[3])
        : "r"(a[0]), "r"(a[1]), "r"(a[2]), "r"(a[3]), "r"(b0), "r"(b1));
}
__device__ __forceinline__ uint32_t fp_order(float f) {
    uint32_t u = __float_as_uint(f);
    return u ^ ((u >> 31) ? 0xFFFFFFFFu : 0x80000000u);
}
__device__ __forceinline__ float fp_unorder(uint32_t e) {
    uint32_t u = (e >> 31) ? (e ^ 0x80000000u) : ~e;
    return __uint_as_float(u);
}

// ---------------- prep: fp16 codebook, norms, error-bound norms ----------------
__global__ void prep_kernel(const float* __restrict__ cb) {
    int k = blockIdx.x, d = threadIdx.x;
    float v = cb[k * DDIM + d];
    __half h = __float2half_rn(v);
    g_cbh[k * DDIM + d] = h;
    float hf = __half2float(h);
    float cl = v - hf;
    float s = v * v, s2 = cl * cl, s3 = hf * hf;
#pragma unroll
    for (int o = 16; o; o >>= 1) {
        s  += __shfl_xor_sync(~0u, s,  o);
        s2 += __shfl_xor_sync(~0u, s2, o);
        s3 += __shfl_xor_sync(~0u, s3, o);
    }
    __shared__ float ws[4][3];
    if ((threadIdx.x & 31) == 0) {
        int w = threadIdx.x >> 5;
        ws[w][0] = s; ws[w][1] = s2; ws[w][2] = s3;
    }
    __syncthreads();
    if (threadIdx.x == 0) {
        g_cnorm[k] = ws[0][0] + ws[1][0] + ws[2][0] + ws[3][0];
        float ncl = sqrtf(ws[0][1] + ws[1][1] + ws[2][1] + ws[3][1]);
        float nch = sqrtf(ws[0][2] + ws[1][2] + ws[2][2] + ws[3][2]);
        atomicMax(&g_maxcl_bits, __float_as_uint(ncl));
        atomicMax(&g_maxch_bits, __float_as_uint(nch));
    }
}

extern __shared__ char smem[];

__device__ __forceinline__ void issue_b_tile(uint32_t sb, int nt, int st, int tid) {
#pragma unroll
    for (int i = 0; i < 4; i++) {
        int ch  = i * NTHREADS + tid;          // 2048 chunks of 16B
        int row = ch >> 4;                     // code row (128 rows x 16 chunks)
        int c16 = ch & 15;
        const __half* src = g_cbh + ((size_t)(nt * NTILE + row) * DDIM + c16 * 8);
        uint32_t dst = sb + SM_B + (uint32_t)st * B_SZ
                     + (uint32_t)row * PITCH + (uint32_t)c16 * 16u;
        cp_async16(dst, src);
    }
    cp_commit();
}

__global__ __launch_bounds__(NTHREADS, 1) void vq_mma_kernel(
    const float* __restrict__ x, const float* __restrict__ cb, float* __restrict__ out)
{
    const uint32_t sb = smem_u32(smem);
    const int tid  = threadIdx.x;
    const int lane = tid & 31;
    const int warp = tid >> 5;
    const int wm   = warp >> 2;
    const int wn   = warp & 3;
    const int m0   = blockIdx.x * MT;

    unsigned*           rowmin  = reinterpret_cast<unsigned*>(smem + SM_RMIN);
    float*              wrow    = reinterpret_cast<float*>(smem + SM_WROW);
    unsigned long long* rowbest = reinterpret_cast<unsigned long long*>(smem + SM_RBEST);
    unsigned*           qn      = reinterpret_cast<unsigned*>(smem + SM_QN);
    unsigned*           queue   = reinterpret_cast<unsigned*>(smem + SM_QUEUE);

    issue_b_tile(sb, 0, 0, tid);
    issue_b_tile(sb, 1, 1, tid);

    // ---- prologue: x -> SM_X, convert hi -> AH (padded rows), norms + windows ----
    {
        const float4* xsrc = reinterpret_cast<const float4*>(x + (size_t)m0 * DDIM);
        float4* xs4 = reinterpret_cast<float4*>(smem + SM_X);
#pragma unroll
        for (int i = 0; i < 8; i++) xs4[i * NTHREADS + tid] = xsrc[i * NTHREADS + tid];
        __syncthreads();
        const float* xs = reinterpret_cast<const float*>(smem + SM_X);
#pragma unroll
        for (int i = 0; i < 4; i++) {
            int oc  = i * NTHREADS + tid;      // 2048 fp16 chunks (16B = 8 halfs)
            int row = oc >> 4;
            int hc  = oc & 15;
            const float* p = xs + row * DDIM + hc * 8;
            uint32_t hi[4];
#pragma unroll
            for (int j = 0; j < 4; j++) {
                __half h0 = __float2half_rn(p[j * 2]);
                __half h1 = __float2half_rn(p[j * 2 + 1]);
                hi[j] = ((uint32_t)__half_as_ushort(h1) << 16) | __half_as_ushort(h0);
            }
            *reinterpret_cast<uint4*>(smem + SM_AH + row * PITCH + hc * 16) =
                make_uint4(hi[0], hi[1], hi[2], hi[3]);
        }
        {   // per-row ||x||, ||x - fl16(x)|| -> rigorous window
            int row  = tid >> 2;
            int part = tid & 3;
            const float* p = xs + row * DDIM + part * 32;
            float s = 0.f, sl = 0.f;
#pragma unroll
            for (int q = 0; q < 32; q++) {
                float v  = p[q];
                float lv = v - __half2float(__float2half_rn(v));
                s  = fmaf(v, v, s);
                sl = fmaf(lv, lv, sl);
            }
            s  += __shfl_xor_sync(~0u, s, 1);  s  += __shfl_xor_sync(~0u, s, 2);
            sl += __shfl_xor_sync(~0u, sl, 1); sl += __shfl_xor_sync(~0u, sl, 2);
            if (part == 0) {
                float mcl = __uint_as_float(g_maxcl_bits);
                float mch = __uint_as_float(g_maxch_bits);
                float nx = sqrtf(s), nxl = sqrtf(sl);
                wrow[row] = 4.f * ((nx + nxl) * mcl + nxl * (mch + mcl)) + 2e-3f;
            }
        }
        if (tid < MT) { rowmin[tid] = 0xFFFFFFFFu; rowbest[tid] = ~0ull; }
        if (tid == 0) qn[0] = 0;
        __syncthreads();
    }

    // per-slot: best score + exact code idx, uu = lower bound on untracked
    float sm1[4], uu[4];
    int   i1[4];
#pragma unroll
    for (int s = 0; s < 4; s++) { sm1[s] = 3.4e38f; uu[s] = 3.4e38f; i1[s] = 0; }

    const int t8 = lane >> 3;
    const int j8 = lane & 7;

    // precomputed ldsm row bases (linear addressing, no XOR)
    const uint32_t c16off = (uint32_t)(t8 >> 1) * 16u;
    uint32_t a_base[2], b_base[2];
#pragma unroll
    for (int mi = 0; mi < 2; mi++)
        a_base[mi] = sb + SM_AH + (uint32_t)(wm * 32 + mi * 16 + (t8 & 1) * 8 + j8) * PITCH + c16off;
#pragma unroll
    for (int bi = 0; bi < 2; bi++)
        b_base[bi] = (uint32_t)(wn * 32 + bi * 16 + (t8 & 1) * 8 + j8) * PITCH + c16off;

    for (int nt = 0; nt < NT_CNT; nt++) {
        if (nt + 1 < NT_CNT) cp_wait<1>(); else cp_wait<0>();
        __syncthreads();
        if (nt + 2 < NT_CNT) issue_b_tile(sb, nt + 2, (nt + 2) % 3, tid);

        const uint32_t bhb = sb + SM_B + (uint32_t)(nt % 3) * B_SZ;

        float acc[2][4][4];
#pragma unroll
        for (int mi = 0; mi < 2; mi++)
#pragma unroll
            for (int ni = 0; ni < 4; ni++)
#pragma unroll
                for (int c = 0; c < 4; c++) acc[mi][ni][c] = 0.f;

#pragma unroll
        for (int kc = 0; kc < 8; kc++) {
            const uint32_t ko = (uint32_t)kc * 32u;      // c16 advances by 2 per kc
            uint32_t ah[2][4];
#pragma unroll
            for (int mi = 0; mi < 2; mi++)
                ldsm4(ah[mi][0], ah[mi][1], ah[mi][2], ah[mi][3], a_base[mi] + ko);
            uint32_t bh[2][4];
#pragma unroll
            for (int bi = 0; bi < 2; bi++)
                ldsm4(bh[bi][0], bh[bi][1], bh[bi][2], bh[bi][3], bhb + b_base[bi] + ko);
#pragma unroll
            for (int mi = 0; mi < 2; mi++)
#pragma unroll
                for (int ni = 0; ni < 4; ni++) {
                    int bi = ni >> 1, sub = ni & 1;
                    mma_f32(acc[mi][ni], ah[mi], bh[bi][sub], bh[bi][sub + 2]);
                }
        }

        // ---- fold: per slot 8 scores; track (sm1,i1) exact and uu bound ----
        float cn0[4], cn1[4];
#pragma unroll
        for (int ni = 0; ni < 4; ni++) {
            int col0 = nt * NTILE + wn * 32 + ni * 8 + 2 * (lane & 3);
            cn0[ni] = __ldg(&g_cnorm[col0]);
            cn1[ni] = __ldg(&g_cnorm[col0 + 1]);
        }
        const int base = nt * NTILE + wn * 32 + 2 * (lane & 3);
#pragma unroll
        for (int mi = 0; mi < 2; mi++)
#pragma unroll
            for (int h = 0; h < 2; h++) {
                const int s = mi * 2 + h;
                float sc[8];
#pragma unroll
                for (int ni = 0; ni < 4; ni++) {
                    sc[ni * 2]     = fmaf(-2.f, acc[mi][ni][2 * h],     cn0[ni]);
                    sc[ni * 2 + 1] = fmaf(-2.f, acc[mi][ni][2 * h + 1], cn1[ni]);
                }
                float m = sc[0];
#pragma unroll
                for (int j = 1; j < 8; j++) m = fminf(m, sc[j]);
                if (m < sm1[s]) {
                    int jm = 7;
#pragma unroll
                    for (int j = 7; j >= 0; j--) if (sc[j] == m) jm = j;
                    float t2 = 3.4e38f;
#pragma unroll
                    for (int j = 0; j < 8; j++) t2 = (j == jm) ? t2 : fminf(t2, sc[j]);
                    uu[s] = fminf(uu[s], fminf(sm1[s], t2));
                    sm1[s] = m;
                    i1[s] = base + (jm >> 1) * 8 + (jm & 1);
                } else {
                    uu[s] = fminf(uu[s], m);
                }
            }
    }

    // ---- row approx min ----
#pragma unroll
    for (int s = 0; s < 4; s++) {
        int row = wm * 32 + (s >> 1) * 16 + (s & 1) * 8 + (lane >> 2);
        atomicMin(&rowmin[row], fp_order(sm1[s]));
    }
    __syncthreads();

    // ---- push candidates: single codes + rare slot fallbacks ----
    const int cbase = wn * 32 + 2 * (lane & 3);
#pragma unroll
    for (int s = 0; s < 4; s++) {
        int row = wm * 32 + (s >> 1) * 16 + (s & 1) * 8 + (lane >> 2);
        float thr = fp_unorder(rowmin[row]) + wrow[row];
        if (sm1[s] <= thr) {
            unsigned slot = atomicAdd(qn, 1u);
            if (slot < QCAP) queue[slot] = ((unsigned)row << 10) | (unsigned)i1[s];
        }
        if (uu[s] <= thr) {
            unsigned slot = atomicAdd(qn, 1u);
            if (slot < QCAP) queue[slot] = 0x80000000u | ((unsigned)row << 7) | (unsigned)cbase;
        }
    }
    __syncthreads();

    // ---- rescue workers ----
    {
        int nq = (int)min(qn[0], (unsigned)QCAP);
        const float* xsf = reinterpret_cast<const float*>(smem + SM_X);
        for (int it = warp; it < nq; it += 16) {
            unsigned item = queue[it];
            if (!(item & 0x80000000u)) {
                // single code: warp-cooperative, 1 float4 per lane
                int row  = (int)(item >> 10);
                int code = (int)(item & 1023u);
                float4 a = reinterpret_cast<const float4*>(xsf + row * DDIM)[lane];
                float4 b = __ldg(&reinterpret_cast<const float4*>(cb + (size_t)code * DDIM)[lane]);
                float d = a.x * b.x + a.y * b.y + a.z * b.z + a.w * b.w;
#pragma unroll
                for (int o = 16; o; o >>= 1) d += __shfl_xor_sync(~0u, d, o);
                if (lane == 0) {
                    float se = fmaf(-2.f, d, __ldg(&g_cnorm[code]));
                    atomicMin(&rowbest[row],
                              ((unsigned long long)fp_order(se) << 32) | (uint32_t)code);
                }
            } else {
                // slot fallback: 64 codes, 2 per lane, per-lane serial dot
                int row = (int)((item >> 7) & 127u);
                int cb0 = (int)(item & 127u);
                const float4* xr = reinterpret_cast<const float4*>(xsf + row * DDIM);
#pragma unroll
                for (int t = 0; t < 2; t++) {
                    int e = lane + t * 32;
                    int code = (e >> 3) * NTILE + ((e >> 1) & 3) * 8 + (e & 1) + cb0;
                    const float4* cr = reinterpret_cast<const float4*>(cb + (size_t)code * DDIM);
                    float d0 = 0.f, d1 = 0.f, d2 = 0.f, d3 = 0.f;
#pragma unroll
                    for (int q = 0; q < 8; q++) {
                        float4 a0 = xr[q * 4 + 0], b0 = __ldg(&cr[q * 4 + 0]);
                        float4 a1 = xr[q * 4 + 1], b1 = __ldg(&cr[q * 4 + 1]);
                        float4 a2 = xr[q * 4 + 2], b2 = __ldg(&cr[q * 4 + 2]);
                        float4 a3 = xr[q * 4 + 3], b3 = __ldg(&cr[q * 4 + 3]);
                        d0 = fmaf(a0.x, b0.x, d0); d0 = fmaf(a0.y, b0.y, d0);
                        d0 = fmaf(a0.z, b0.z, d0); d0 = fmaf(a0.w, b0.w, d0);
                        d1 = fmaf(a1.x, b1.x, d1); d1 = fmaf(a1.y, b1.y, d1);
                        d1 = fmaf(a1.z, b1.z, d1); d1 = fmaf(a1.w, b1.w, d1);
                        d2 = fmaf(a2.x, b2.x, d2); d2 = fmaf(a2.y, b2.y, d2);
                        d2 = fmaf(a2.z, b2.z, d2); d2 = fmaf(a2.w, b2.w, d2);
                        d3 = fmaf(a3.x, b3.x, d3); d3 = fmaf(a3.y, b3.y, d3);
                        d3 = fmaf(a3.w, b3.w, d3); d3 = fmaf(a3.z, b3.z, d3);
                    }
                    float d = (d0 + d1) + (d2 + d3);
                    float se = fmaf(-2.f, d, __ldg(&g_cnorm[code]));
                    atomicMin(&rowbest[row],
                              ((unsigned long long)fp_order(se) << 32) | (uint32_t)code);
                }
            }
        }
    }
    __syncthreads();

    // ---- output: out = x + (q - x), x from SMEM ----
    const float4* cb4 = reinterpret_cast<const float4*>(cb);
    const float4* xs4 = reinterpret_cast<const float4*>(smem + SM_X);
    float4* o4 = reinterpret_cast<float4*>(out);
#pragma unroll
    for (int i = 0; i < 8; i++) {
        int g  = i * NTHREADS + tid;
        int r  = g >> 5, c4 = g & 31;
        int bi = (int)(rowbest[r] & 0xFFFFFFFFu);
        float4 xv = xs4[r * 32 + c4];
        float4 qv = cb4[(size_t)bi * 32 + c4];
        float4 ov;
        ov.x = xv.x + (qv.x - xv.x);
        ov.y = xv.y + (qv.y - xv.y);
        ov.z = xv.z + (qv.z - xv.z);
        ov.w = xv.w + (qv.w - xv.w);
        o4[(size_t)(m0 + r) * 32 + c4] = ov;
    }
}

extern "C" void kernel_launch(void* const* d_in, const int* in_sizes, int n_in,
                              void* d_out, int out_size) {
    const float* x  = (const float*)d_in[0];
    const float* cb = (const float*)d_in[1];
    float* out = (float*)d_out;
    int N = in_sizes[0] / DDIM;     // 32768
    int K = in_sizes[1] / DDIM;     // 1024

    prep_kernel<<<K, DDIM>>>(cb);

    cudaFuncSetAttribute(vq_mma_kernel, cudaFuncAttributeMaxDynamicSharedMemorySize, SMEM_BYTES);
    vq_mma_kernel<<<N / MT, NTHREADS, SMEM_BYTES>>>(x, cb, out);
}

// round 16
// speedup vs baseline: 1.1373x; 1.0949x over previous
#include <cuda_runtime.h>
#include <cuda_fp16.h>
#include <cstdint>

// N=32768, D=128, K=1024. scores = ||c||^2 - 2 x.c
// Round 16 = round 11 (best: 75.8us) + micro-cuts:
//  (a) hoisted SW128 ldsm addressing (shared XOR term, precomputed row bases)
//  (b) x prologue staged via cp.async (overlaps B prefetch)
//  (c) one fewer prologue barrier
// Phase A: single fp16 HMMA (xh*ch, fp32 acc); fold tracks per-(lane,slot)
//   best score + exact code idx + uu lower bound on untracked codes.
// Phase B: provable window rescue (single-code warp-coop + rare slot
//   fallback), exact fp32 rescore, packed u64 atomicMin (low-index ties).

#define DDIM     128
#define KCODES   1024
#define MT       128
#define NTILE    128
#define NT_CNT   (KCODES / NTILE)   // 8
#define NTHREADS 512
#define QCAP     4096

__device__ __half   g_cbh[KCODES * DDIM];
__device__ float    g_cnorm[KCODES];
__device__ unsigned g_maxcl_bits = 0;
__device__ unsigned g_maxch_bits = 0;

// ---------------- SMEM layout (bytes) ----------------
#define SM_AH    0         // xh tile, swizzled fp16: 32KB
#define SM_B     32768     // B ring: 3 x 32KB = 96KB
#define SM_X     131072    // x tile fp32: 64KB
#define SM_RMIN  196608    // rowmin u32 [128]
#define SM_WROW  197120    // W_row float [128]
#define SM_RBEST 197632    // rowbest u64 [128]
#define SM_QN    198656    // queue count + pad
#define SM_QUEUE 198784    // u32 items [QCAP] = 16KB
#define SMEM_BYTES (198784 + QCAP * 4)

__device__ __forceinline__ uint32_t smem_u32(const void* p) {
    uint32_t a;
    asm("{ .reg .u64 t; cvta.to.shared.u64 t, %1; cvt.u32.u64 %0, t; }" : "=r"(a) : "l"(p));
    return a;
}
__device__ __forceinline__ void cp_async16(uint32_t dst, const void* src) {
    asm volatile("cp.async.cg.shared.global [%0], [%1], 16;" :: "r"(dst), "l"(src) : "memory");
}
__device__ __forceinline__ void cp_commit() {
    asm volatile("cp.async.commit_group;" ::: "memory");
}
template <int W>
__device__ __forceinline__ void cp_wait() {
    asm volatile("cp.async.wait_group %0;" :: "n"(W) : "memory");
}
__device__ __forceinline__ void ldsm4(uint32_t& r0, uint32_t& r1, uint32_t& r2, uint32_t& r3,
                                      uint32_t addr) {
    asm volatile("ldmatrix.sync.aligned.m8n8.x4.shared.b16 {%0,%1,%2,%3}, [%4];"
                 : "=r"(r0), "=r"(r1), "=r"(r2), "=r"(r3) : "r"(addr));
}
__device__ __forceinline__ void mma_f32(float* c, const uint32_t* a, uint32_t b0, uint32_t b1) {
    asm volatile(
        "mma.sync.aligned.m16n8k16.row.col.f32.f16.f16.f32 "
        "{%0,%1,%2,%3}, {%4,%5,%6,%7}, {%8,%9}, {%0,%1,%2,%3};"
        : "+f"(c[0]), "+f"(c[1]), "+f"(c[2]), "+f"(c[3])
        : "r"(a[0]), "r"(a[1]), "r"(a[2]), "r"(a[3]), "r"(b0), "r"(b1));
}
__device__ __forceinline__ uint32_t fp_order(float f) {
    uint32_t u = __float_as_uint(f);
    return u ^ ((u >> 31) ? 0xFFFFFFFFu : 0x80000000u);
}
__device__ __forceinline__ float fp_unorder(uint32_t e) {
    uint32_t u = (e >> 31) ? (e ^ 0x80000000u) : ~e;
    return __uint_as_float(u);
}

// ---------------- prep: fp16 codebook, norms, error-bound norms ----------------
__global__ void prep_kernel(const float* __restrict__ cb) {
    int k = blockIdx.x, d = threadIdx.x;
    float v = cb[k * DDIM + d];
    __half h = __float2half_rn(v);
    g_cbh[k * DDIM + d] = h;
    float hf = __half2float(h);
    float cl = v - hf;
    float s = v * v, s2 = cl * cl, s3 = hf * hf;
#pragma unroll
    for (int o = 16; o; o >>= 1) {
        s  += __shfl_xor_sync(~0u, s,  o);
        s2 += __shfl_xor_sync(~0u, s2, o);
        s3 += __shfl_xor_sync(~0u, s3, o);
    }
    __shared__ float ws[4][3];
    if ((threadIdx.x & 31) == 0) {
        int w = threadIdx.x >> 5;
        ws[w][0] = s; ws[w][1] = s2; ws[w][2] = s3;
    }
    __syncthreads();
    if (threadIdx.x == 0) {
        g_cnorm[k] = ws[0][0] + ws[1][0] + ws[2][0] + ws[3][0];
        float ncl = sqrtf(ws[0][1] + ws[1][1] + ws[2][1] + ws[3][1]);
        float nch = sqrtf(ws[0][2] + ws[1][2] + ws[2][2] + ws[3][2]);
        atomicMax(&g_maxcl_bits, __float_as_uint(ncl));
        atomicMax(&g_maxch_bits, __float_as_uint(nch));
    }
}

extern __shared__ char smem[];

__device__ __forceinline__ void issue_b_tile(uint32_t sb, int nt, int st, int tid) {
#pragma unroll
    for (int i = 0; i < 4; i++) {
        int ch  = i * NTHREADS + tid;          // 2048 chunks of 16B
        int row = ch >> 4;
        int c16 = ch & 15;
        const __half* src = g_cbh + ((size_t)(nt * NTILE + row) * DDIM + c16 * 8);
        uint32_t dst = sb + SM_B + (uint32_t)st * 32768u
                     + (uint32_t)(row * 16 + (c16 ^ (row & 7))) * 16u;
        cp_async16(dst, src);
    }
    cp_commit();
}

__global__ __launch_bounds__(NTHREADS, 1) void vq_mma_kernel(
    const float* __restrict__ x, const float* __restrict__ cb, float* __restrict__ out)
{
    const uint32_t sb = smem_u32(smem);
    const int tid  = threadIdx.x;
    const int lane = tid & 31;
    const int warp = tid >> 5;
    const int wm   = warp >> 2;
    const int wn   = warp & 3;
    const int m0   = blockIdx.x * MT;

    unsigned*           rowmin  = reinterpret_cast<unsigned*>(smem + SM_RMIN);
    float*              wrow    = reinterpret_cast<float*>(smem + SM_WROW);
    unsigned long long* rowbest = reinterpret_cast<unsigned long long*>(smem + SM_RBEST);
    unsigned*           qn      = reinterpret_cast<unsigned*>(smem + SM_QN);
    unsigned*           queue   = reinterpret_cast<unsigned*>(smem + SM_QUEUE);

    // (b) stage x via cp.async (group 0), then B0 (group 1), B1 (group 2)
    {
        const float* xsrc = x + (size_t)m0 * DDIM;
#pragma unroll
        for (int i = 0; i < 8; i++) {
            int ch = i * NTHREADS + tid;       // 4096 chunks of 16B
            cp_async16(sb + SM_X + (uint32_t)ch * 16u, xsrc + ch * 4);
        }
        cp_commit();
    }
    issue_b_tile(sb, 0, 0, tid);
    issue_b_tile(sb, 1, 1, tid);

    // ---- prologue: convert hi -> AH from SM_X, row norms + windows ----
    {
        cp_wait<2>();              // x staged (B0/B1 may still be in flight)
        __syncthreads();
        const float* xs = reinterpret_cast<const float*>(smem + SM_X);
#pragma unroll
        for (int i = 0; i < 4; i++) {
            int oc  = i * NTHREADS + tid;      // 2048 fp16 chunks (16B = 8 halfs)
            int row = oc >> 4;
            int hc  = oc & 15;
            const float* p = xs + row * DDIM + hc * 8;
            uint32_t hi[4];
#pragma unroll
            for (int j = 0; j < 4; j++) {
                __half h0 = __float2half_rn(p[j * 2]);
                __half h1 = __float2half_rn(p[j * 2 + 1]);
                hi[j] = ((uint32_t)__half_as_ushort(h1) << 16) | __half_as_ushort(h0);
            }
            uint32_t chunk = (uint32_t)(row * 16 + (hc ^ (row & 7))) * 16u;
            *reinterpret_cast<uint4*>(smem + SM_AH + chunk) = make_uint4(hi[0], hi[1], hi[2], hi[3]);
        }
        {   // per-row ||x||, ||x - fl16(x)|| -> rigorous window
            int row  = tid >> 2;
            int part = tid & 3;
            const float* p = xs + row * DDIM + part * 32;
            float s = 0.f, sl = 0.f;
#pragma unroll
            for (int q = 0; q < 32; q++) {
                float v  = p[q];
                float lv = v - __half2float(__float2half_rn(v));
                s  = fmaf(v, v, s);
                sl = fmaf(lv, lv, sl);
            }
            s  += __shfl_xor_sync(~0u, s, 1);  s  += __shfl_xor_sync(~0u, s, 2);
            sl += __shfl_xor_sync(~0u, sl, 1); sl += __shfl_xor_sync(~0u, sl, 2);
            if (part == 0) {
                float mcl = __uint_as_float(g_maxcl_bits);
                float mch = __uint_as_float(g_maxch_bits);
                float nx = sqrtf(s), nxl = sqrtf(sl);
                wrow[row] = 4.f * ((nx + nxl) * mcl + nxl * (mch + mcl)) + 2e-3f;
            }
        }
        if (tid < MT) { rowmin[tid] = 0xFFFFFFFFu; rowbest[tid] = ~0ull; }
        if (tid == 0) qn[0] = 0;
        __syncthreads();
    }

    // per-slot: best score + exact code idx, uu = lower bound on untracked
    float sm1[4], uu[4];
    int   i1[4];
#pragma unroll
    for (int s = 0; s < 4; s++) { sm1[s] = 3.4e38f; uu[s] = 3.4e38f; i1[s] = 0; }

    const int t8  = lane >> 3;
    const int j8  = lane & 7;
    const int t8h = t8 >> 1;

    // (a) hoisted ldsm addressing: row&7 == j8 for all 4 bases, so the XOR
    // term ((kc*2+t8h)^j8)*16 is shared; row bases precomputed once.
    uint32_t a_base[2], b_rowoff[2];
#pragma unroll
    for (int mi = 0; mi < 2; mi++) {
        int row = wm * 32 + mi * 16 + (t8 & 1) * 8 + j8;
        a_base[mi] = sb + SM_AH + (uint32_t)row * 256u;
    }
#pragma unroll
    for (int bi = 0; bi < 2; bi++) {
        int nrow = wn * 32 + bi * 16 + (t8 & 1) * 8 + j8;
        b_rowoff[bi] = (uint32_t)nrow * 256u;
    }

    for (int nt = 0; nt < NT_CNT; nt++) {
        if (nt + 1 < NT_CNT) cp_wait<1>(); else cp_wait<0>();
        __syncthreads();
        if (nt + 2 < NT_CNT) issue_b_tile(sb, nt + 2, (nt + 2) % 3, tid);

        const uint32_t bhb = sb + SM_B + (uint32_t)(nt % 3) * 32768u;

        float acc[2][4][4];
#pragma unroll
        for (int mi = 0; mi < 2; mi++)
#pragma unroll
            for (int ni = 0; ni < 4; ni++)
#pragma unroll
                for (int c = 0; c < 4; c++) acc[mi][ni][c] = 0.f;

#pragma unroll
        for (int kc = 0; kc < 8; kc++) {
            const uint32_t xo = (uint32_t)(((kc * 2 + t8h) ^ j8) << 4);
            uint32_t ah[2][4];
#pragma unroll
            for (int mi = 0; mi < 2; mi++)
                ldsm4(ah[mi][0], ah[mi][1], ah[mi][2], ah[mi][3], a_base[mi] + xo);
            uint32_t bh[2][4];
#pragma unroll
            for (int bi = 0; bi < 2; bi++)
                ldsm4(bh[bi][0], bh[bi][1], bh[bi][2], bh[bi][3], bhb + b_rowoff[bi] + xo);
#pragma unroll
            for (int mi = 0; mi < 2; mi++)
#pragma unroll
                for (int ni = 0; ni < 4; ni++) {
                    int bi = ni >> 1, sub = ni & 1;
                    mma_f32(acc[mi][ni], ah[mi], bh[bi][sub], bh[bi][sub + 2]);
                }
        }

        // ---- fold: per slot 8 scores; track (sm1,i1) exact and uu bound ----
        float cn0[4], cn1[4];
#pragma unroll
        for (int ni = 0; ni < 4; ni++) {
            int col0 = nt * NTILE + wn * 32 + ni * 8 + 2 * (lane & 3);
            cn0[ni] = __ldg(&g_cnorm[col0]);
            cn1[ni] = __ldg(&g_cnorm[col0 + 1]);
        }
        const int base = nt * NTILE + wn * 32 + 2 * (lane & 3);
#pragma unroll
        for (int mi = 0; mi < 2; mi++)
#pragma unroll
            for (int h = 0; h < 2; h++) {
                const int s = mi * 2 + h;
                float sc[8];
#pragma unroll
                for (int ni = 0; ni < 4; ni++) {
                    sc[ni * 2]     = fmaf(-2.f, acc[mi][ni][2 * h],     cn0[ni]);
                    sc[ni * 2 + 1] = fmaf(-2.f, acc[mi][ni][2 * h + 1], cn1[ni]);
                }
                float m = sc[0];
#pragma unroll
                for (int j = 1; j < 8; j++) m = fminf(m, sc[j]);
                if (m < sm1[s]) {
                    int jm = 7;
#pragma unroll
                    for (int j = 7; j >= 0; j--) if (sc[j] == m) jm = j;
                    float t2 = 3.4e38f;
#pragma unroll
                    for (int j = 0; j < 8; j++) t2 = (j == jm) ? t2 : fminf(t2, sc[j]);
                    uu[s] = fminf(uu[s], fminf(sm1[s], t2));
                    sm1[s] = m;
                    i1[s] = base + (jm >> 1) * 8 + (jm & 1);
                } else {
                    uu[s] = fminf(uu[s], m);
                }
            }
    }

    // ---- row approx min ----
#pragma unroll
    for (int s = 0; s < 4; s++) {
        int row = wm * 32 + (s >> 1) * 16 + (s & 1) * 8 + (lane >> 2);
        atomicMin(&rowmin[row], fp_order(sm1[s]));
    }
    __syncthreads();

    // ---- push candidates: single codes + rare slot fallbacks ----
    const int cbase = wn * 32 + 2 * (lane & 3);
#pragma unroll
    for (int s = 0; s < 4; s++) {
        int row = wm * 32 + (s >> 1) * 16 + (s & 1) * 8 + (lane >> 2);
        float thr = fp_unorder(rowmin[row]) + wrow[row];
        if (sm1[s] <= thr) {
            unsigned slot = atomicAdd(qn, 1u);
            if (slot < QCAP) queue[slot] = ((unsigned)row << 10) | (unsigned)i1[s];
        }
        if (uu[s] <= thr) {
            unsigned slot = atomicAdd(qn, 1u);
            if (slot < QCAP) queue[slot] = 0x80000000u | ((unsigned)row << 7) | (unsigned)cbase;
        }
    }
    __syncthreads();

    // ---- rescue workers ----
    {
        int nq = (int)min(qn[0], (unsigned)QCAP);
        const float* xsf = reinterpret_cast<const float*>(smem + SM_X);
        for (int it = warp; it < nq; it += 16) {
            unsigned item = queue[it];
            if (!(item & 0x80000000u)) {
                // single code: warp-cooperative, 1 float4 per lane
                int row  = (int)(item >> 10);
                int code = (int)(item & 1023u);
                float4 a = reinterpret_cast<const float4*>(xsf + row * DDIM)[lane];
                float4 b = __ldg(&reinterpret_cast<const float4*>(cb + (size_t)code * DDIM)[lane]);
                float d = a.x * b.x + a.y * b.y + a.z * b.z + a.w * b.w;
#pragma unroll
                for (int o = 16; o; o >>= 1) d += __shfl_xor_sync(~0u, d, o);
                if (lane == 0) {
                    float se = fmaf(-2.f, d, __ldg(&g_cnorm[code]));
                    atomicMin(&rowbest[row],
                              ((unsigned long long)fp_order(se) << 32) | (uint32_t)code);
                }
            } else {
                // slot fallback: 64 codes, 2 per lane, per-lane serial dot
                int row = (int)((item >> 7) & 127u);
                int cb0 = (int)(item & 127u);
                const float4* xr = reinterpret_cast<const float4*>(xsf + row * DDIM);
#pragma unroll
                for (int t = 0; t < 2; t++) {
                    int e = lane + t * 32;
                    int code = (e >> 3) * NTILE + ((e >> 1) & 3) * 8 + (e & 1) + cb0;
                    const float4* cr = reinterpret_cast<const float4*>(cb + (size_t)code * DDIM);
                    float d0 = 0.f, d1 = 0.f, d2 = 0.f, d3 = 0.f;
#pragma unroll
                    for (int q = 0; q < 8; q++) {
                        float4 a0 = xr[q * 4 + 0], b0 = __ldg(&cr[q * 4 + 0]);
                        float4 a1 = xr[q * 4 + 1], b1 = __ldg(&cr[q * 4 + 1]);
                        float4 a2 = xr[q * 4 + 2], b2 = __ldg(&cr[q * 4 + 2]);
                        float4 a3 = xr[q * 4 + 3], b3 = __ldg(&cr[q * 4 + 3]);
                        d0 = fmaf(a0.x, b0.x, d0); d0 = fmaf(a0.y, b0.y, d0);
                        d0 = fmaf(a0.z, b0.z, d0); d0 = fmaf(a0.w, b0.w, d0);
                        d1 = fmaf(a1.x, b1.x, d1); d1 = fmaf(a1.y, b1.y, d1);
                        d1 = fmaf(a1.z, b1.z, d1); d1 = fmaf(a1.w, b1.w, d1);
                        d2 = fmaf(a2.x, b2.x, d2); d2 = fmaf(a2.y, b2.y, d2);
                        d2 = fmaf(a2.z, b2.z, d2); d2 = fmaf(a2.w, b2.w, d2);
                        d3 = fmaf(a3.x, b3.x, d3); d3 = fmaf(a3.y, b3.y, d3);
                        d3 = fmaf(a3.z, b3.z, d3); d3 = fmaf(a3.w, b3.w, d3);
                    }
                    float d = (d0 + d1) + (d2 + d3);
                    float se = fmaf(-2.f, d, __ldg(&g_cnorm[code]));
                    atomicMin(&rowbest[row],
                              ((unsigned long long)fp_order(se) << 32) | (uint32_t)code);
                }
            }
        }
    }
    __syncthreads();

    // ---- output: out = x + (q - x), x from SMEM ----
    const float4* cb4 = reinterpret_cast<const float4*>(cb);
    const float4* xs4 = reinterpret_cast<const float4*>(smem + SM_X);
    float4* o4 = reinterpret_cast<float4*>(out);
#pragma unroll
    for (int i = 0; i < 8; i++) {
        int g  = i * NTHREADS + tid;
        int r  = g >> 5, c4 = g & 31;
        int bi = (int)(rowbest[r] & 0xFFFFFFFFu);
        float4 xv = xs4[r * 32 + c4];
        float4 qv = cb4[(size_t)bi * 32 + c4];
        float4 ov;
        ov.x = xv.x + (qv.x - xv.x);
        ov.y = xv.y + (qv.y - xv.y);
        ov.z = xv.z + (qv.z - xv.z);
        ov.w = xv.w + (qv.w - xv.w);
        o4[(size_t)(m0 + r) * 32 + c4] = ov;
    }
}

extern "C" void kernel_launch(void* const* d_in, const int* in_sizes, int n_in,
                              void* d_out, int out_size) {
    const float* x  = (const float*)d_in[0];
    const float* cb = (const float*)d_in[1];
    float* out = (float*)d_out;
    int N = in_sizes[0] / DDIM;     // 32768
    int K = in_sizes[1] / DDIM;     // 1024

    prep_kernel<<<K, DDIM>>>(cb);

    cudaFuncSetAttribute(vq_mma_kernel, cudaFuncAttributeMaxDynamicSharedMemorySize, SMEM_BYTES);
    vq_mma_kernel<<<N / MT, NTHREADS, SMEM_BYTES>>>(x, cb, out);
}

// round 17
// speedup vs baseline: 1.1383x; 1.0009x over previous
#include <cuda_runtime.h>
#include <cuda_fp16.h>
#include <cstdint>

// N=32768, D=128, K=1024. scores = ||c||^2 - 2 x.c
// Round 17 = round 16 (best: 73.9us) + g_cnorm staged in SMEM (4KB) with
// per-tile prefetch before the MMA loop (kills 256 LDG/thread in the fold's
// dependency chain).
// Phase A: single fp16 HMMA (xh*ch, fp32 acc); fold tracks per-(lane,slot)
//   best score + exact code idx + uu lower bound on untracked codes.
// Phase B: provable window rescue (single-code warp-coop + rare slot
//   fallback), exact fp32 rescore, packed u64 atomicMin (low-index ties).

#define DDIM     128
#define KCODES   1024
#define MT       128
#define NTILE    128
#define NT_CNT   (KCODES / NTILE)   // 8
#define NTHREADS 512
#define QCAP     4096

__device__ __half   g_cbh[KCODES * DDIM];
__device__ float    g_cnorm[KCODES];
__device__ unsigned g_maxcl_bits = 0;
__device__ unsigned g_maxch_bits = 0;

// ---------------- SMEM layout (bytes) ----------------
#define SM_AH    0         // xh tile, swizzled fp16: 32KB
#define SM_B     32768     // B ring: 3 x 32KB = 96KB
#define SM_X     131072    // x tile fp32: 64KB
#define SM_RMIN  196608    // rowmin u32 [128]
#define SM_WROW  197120    // W_row float [128]
#define SM_RBEST 197632    // rowbest u64 [128]
#define SM_QN    198656    // queue count + pad
#define SM_QUEUE 198784    // u32 items [QCAP] = 16KB -> ends 215168
#define SM_CN    215168    // cnorm copy, 1024 floats = 4KB
#define SMEM_BYTES 219264

__device__ __forceinline__ uint32_t smem_u32(const void* p) {
    uint32_t a;
    asm("{ .reg .u64 t; cvta.to.shared.u64 t, %1; cvt.u32.u64 %0, t; }" : "=r"(a) : "l"(p));
    return a;
}
__device__ __forceinline__ void cp_async16(uint32_t dst, const void* src) {
    asm volatile("cp.async.cg.shared.global [%0], [%1], 16;" :: "r"(dst), "l"(src) : "memory");
}
__device__ __forceinline__ void cp_commit() {
    asm volatile("cp.async.commit_group;" ::: "memory");
}
template <int W>
__device__ __forceinline__ void cp_wait() {
    asm volatile("cp.async.wait_group %0;" :: "n"(W) : "memory");
}
__device__ __forceinline__ void ldsm4(uint32_t& r0, uint32_t& r1, uint32_t& r2, uint32_t& r3,
                                      uint32_t addr) {
    asm volatile("ldmatrix.sync.aligned.m8n8.x4.shared.b16 {%0,%1,%2,%3}, [%4];"
                 : "=r"(r0), "=r"(r1), "=r"(r2), "=r"(r3) : "r"(addr));
}
__device__ __forceinline__ void mma_f32(float* c, const uint32_t* a, uint32_t b0, uint32_t b1) {
    asm volatile(
        "mma.sync.aligned.m16n8k16.row.col.f32.f16.f16.f32 "
        "{%0,%1,%2,%3}, {%4,%5,%6,%7}, {%8,%9}, {%0,%1,%2,%3};"
        : "+f"(c[0]), "+f"(c[1]), "+f"(c[2]), "+f"(c[3])
        : "r"(a[0]), "r"(a[1]), "r"(a[2]), "r"(a[3]), "r"(b0), "r"(b1));
}
__device__ __forceinline__ uint32_t fp_order(float f) {
    uint32_t u = __float_as_uint(f);
    return u ^ ((u >> 31) ? 0xFFFFFFFFu : 0x80000000u);
}
__device__ __forceinline__ float fp_unorder(uint32_t e) {
    uint32_t u = (e >> 31) ? (e ^ 0x80000000u) : ~e;
    return __uint_as_float(u);
}

// ---------------- prep: fp16 codebook, norms, error-bound norms ----------------
__global__ void prep_kernel(const float* __restrict__ cb) {
    int k = blockIdx.x, d = threadIdx.x;
    float v = cb[k * DDIM + d];
    __half h = __float2half_rn(v);
    g_cbh[k * DDIM + d] = h;
    float hf = __half2float(h);
    float cl = v - hf;
    float s = v * v, s2 = cl * cl, s3 = hf * hf;
#pragma unroll
    for (int o = 16; o; o >>= 1) {
        s  += __shfl_xor_sync(~0u, s,  o);
        s2 += __shfl_xor_sync(~0u, s2, o);
        s3 += __shfl_xor_sync(~0u, s3, o);
    }
    __shared__ float ws[4][3];
    if ((threadIdx.x & 31) == 0) {
        int w = threadIdx.x >> 5;
        ws[w][0] = s; ws[w][1] = s2; ws[w][2] = s3;
    }
    __syncthreads();
    if (threadIdx.x == 0) {
        g_cnorm[k] = ws[0][0] + ws[1][0] + ws[2][0] + ws[3][0];
        float ncl = sqrtf(ws[0][1] + ws[1][1] + ws[2][1] + ws[3][1]);
        float nch = sqrtf(ws[0][2] + ws[1][2] + ws[2][2] + ws[3][2]);
        atomicMax(&g_maxcl_bits, __float_as_uint(ncl));
        atomicMax(&g_maxch_bits, __float_as_uint(nch));
    }
}

extern __shared__ char smem[];

__device__ __forceinline__ void issue_b_tile(uint32_t sb, int nt, int st, int tid) {
#pragma unroll
    for (int i = 0; i < 4; i++) {
        int ch  = i * NTHREADS + tid;          // 2048 chunks of 16B
        int row = ch >> 4;
        int c16 = ch & 15;
        const __half* src = g_cbh + ((size_t)(nt * NTILE + row) * DDIM + c16 * 8);
        uint32_t dst = sb + SM_B + (uint32_t)st * 32768u
                     + (uint32_t)(row * 16 + (c16 ^ (row & 7))) * 16u;
        cp_async16(dst, src);
    }
    cp_commit();
}

__global__ __launch_bounds__(NTHREADS, 1) void vq_mma_kernel(
    const float* __restrict__ x, const float* __restrict__ cb, float* __restrict__ out)
{
    const uint32_t sb = smem_u32(smem);
    const int tid  = threadIdx.x;
    const int lane = tid & 31;
    const int warp = tid >> 5;
    const int wm   = warp >> 2;
    const int wn   = warp & 3;
    const int m0   = blockIdx.x * MT;

    unsigned*           rowmin  = reinterpret_cast<unsigned*>(smem + SM_RMIN);
    float*              wrow    = reinterpret_cast<float*>(smem + SM_WROW);
    unsigned long long* rowbest = reinterpret_cast<unsigned long long*>(smem + SM_RBEST);
    unsigned*           qn      = reinterpret_cast<unsigned*>(smem + SM_QN);
    unsigned*           queue   = reinterpret_cast<unsigned*>(smem + SM_QUEUE);
    const float*        cnorm_s = reinterpret_cast<const float*>(smem + SM_CN);

    // stage x (64KB) + cnorm (4KB) via cp.async (group 0), then B0, B1
    {
        const float* xsrc = x + (size_t)m0 * DDIM;
#pragma unroll
        for (int i = 0; i < 8; i++) {
            int ch = i * NTHREADS + tid;       // 4096 chunks of 16B
            cp_async16(sb + SM_X + (uint32_t)ch * 16u, xsrc + ch * 4);
        }
        if (tid < 256)
            cp_async16(sb + SM_CN + (uint32_t)tid * 16u, g_cnorm + tid * 4);
        cp_commit();
    }
    issue_b_tile(sb, 0, 0, tid);
    issue_b_tile(sb, 1, 1, tid);

    // ---- prologue: convert hi -> AH from SM_X, row norms + windows ----
    {
        cp_wait<2>();              // x + cnorm staged (B0/B1 may be in flight)
        __syncthreads();
        const float* xs = reinterpret_cast<const float*>(smem + SM_X);
#pragma unroll
        for (int i = 0; i < 4; i++) {
            int oc  = i * NTHREADS + tid;      // 2048 fp16 chunks (16B = 8 halfs)
            int row = oc >> 4;
            int hc  = oc & 15;
            const float* p = xs + row * DDIM + hc * 8;
            uint32_t hi[4];
#pragma unroll
            for (int j = 0; j < 4; j++) {
                __half h0 = __float2half_rn(p[j * 2]);
                __half h1 = __float2half_rn(p[j * 2 + 1]);
                hi[j] = ((uint32_t)__half_as_ushort(h1) << 16) | __half_as_ushort(h0);
            }
            uint32_t chunk = (uint32_t)(row * 16 + (hc ^ (row & 7))) * 16u;
            *reinterpret_cast<uint4*>(smem + SM_AH + chunk) = make_uint4(hi[0], hi[1], hi[2], hi[3]);
        }
        {   // per-row ||x||, ||x - fl16(x)|| -> rigorous window
            int row  = tid >> 2;
            int part = tid & 3;
            const float* p = xs + row * DDIM + part * 32;
            float s = 0.f, sl = 0.f;
#pragma unroll
            for (int q = 0; q < 32; q++) {
                float v  = p[q];
                float lv = v - __half2float(__float2half_rn(v));
                s  = fmaf(v, v, s);
                sl = fmaf(lv, lv, sl);
            }
            s  += __shfl_xor_sync(~0u, s, 1);  s  += __shfl_xor_sync(~0u, s, 2);
            sl += __shfl_xor_sync(~0u, sl, 1); sl += __shfl_xor_sync(~0u, sl, 2);
            if (part == 0) {
                float mcl = __uint_as_float(g_maxcl_bits);
                float mch = __uint_as_float(g_maxch_bits);
                float nx = sqrtf(s), nxl = sqrtf(sl);
                wrow[row] = 4.f * ((nx + nxl) * mcl + nxl * (mch + mcl)) + 2e-3f;
            }
        }
        if (tid < MT) { rowmin[tid] = 0xFFFFFFFFu; rowbest[tid] = ~0ull; }
        if (tid == 0) qn[0] = 0;
        __syncthreads();
    }

    // per-slot: best score + exact code idx, uu = lower bound on untracked
    float sm1[4], uu[4];
    int   i1[4];
#pragma unroll
    for (int s = 0; s < 4; s++) { sm1[s] = 3.4e38f; uu[s] = 3.4e38f; i1[s] = 0; }

    const int t8  = lane >> 3;
    const int j8  = lane & 7;
    const int t8h = t8 >> 1;

    // hoisted ldsm addressing: shared XOR term, precomputed row bases
    uint32_t a_base[2], b_rowoff[2];
#pragma unroll
    for (int mi = 0; mi < 2; mi++) {
        int row = wm * 32 + mi * 16 + (t8 & 1) * 8 + j8;
        a_base[mi] = sb + SM_AH + (uint32_t)row * 256u;
    }
#pragma unroll
    for (int bi = 0; bi < 2; bi++) {
        int nrow = wn * 32 + bi * 16 + (t8 & 1) * 8 + j8;
        b_rowoff[bi] = (uint32_t)nrow * 256u;
    }

    // float2 base index into SMEM cnorm for this lane's column pairs
    const int cn2base = (wn * 32 + 2 * (lane & 3)) >> 1;   // + nt*64 + ni*4
    const float2* cns = reinterpret_cast<const float2*>(smem + SM_CN);

    for (int nt = 0; nt < NT_CNT; nt++) {
        if (nt + 1 < NT_CNT) cp_wait<1>(); else cp_wait<0>();
        __syncthreads();
        if (nt + 2 < NT_CNT) issue_b_tile(sb, nt + 2, (nt + 2) % 3, tid);

        const uint32_t bhb = sb + SM_B + (uint32_t)(nt % 3) * 32768u;

        // prefetch this tile's cnorm pairs (LDS overlaps the MMA block below)
        float2 cnv[4];
#pragma unroll
        for (int ni = 0; ni < 4; ni++) cnv[ni] = cns[nt * 64 + cn2base + ni * 4];

        float acc[2][4][4];
#pragma unroll
        for (int mi = 0; mi < 2; mi++)
#pragma unroll
            for (int ni = 0; ni < 4; ni++)
#pragma unroll
                for (int c = 0; c < 4; c++) acc[mi][ni][c] = 0.f;

#pragma unroll
        for (int kc = 0; kc < 8; kc++) {
            const uint32_t xo = (uint32_t)(((kc * 2 + t8h) ^ j8) << 4);
            uint32_t ah[2][4];
#pragma unroll
            for (int mi = 0; mi < 2; mi++)
                ldsm4(ah[mi][0], ah[mi][1], ah[mi][2], ah[mi][3], a_base[mi] + xo);
            uint32_t bh[2][4];
#pragma unroll
            for (int bi = 0; bi < 2; bi++)
                ldsm4(bh[bi][0], bh[bi][1], bh[bi][2], bh[bi][3], bhb + b_rowoff[bi] + xo);
#pragma unroll
            for (int mi = 0; mi < 2; mi++)
#pragma unroll
                for (int ni = 0; ni < 4; ni++) {
                    int bi = ni >> 1, sub = ni & 1;
                    mma_f32(acc[mi][ni], ah[mi], bh[bi][sub], bh[bi][sub + 2]);
                }
        }

        // ---- fold: per slot 8 scores; track (sm1,i1) exact and uu bound ----
        const int base = nt * NTILE + wn * 32 + 2 * (lane & 3);
#pragma unroll
        for (int mi = 0; mi < 2; mi++)
#pragma unroll
            for (int h = 0; h < 2; h++) {
                const int s = mi * 2 + h;
                float sc[8];
#pragma unroll
                for (int ni = 0; ni < 4; ni++) {
                    sc[ni * 2]     = fmaf(-2.f, acc[mi][ni][2 * h],     cnv[ni].x);
                    sc[ni * 2 + 1] = fmaf(-2.f, acc[mi][ni][2 * h + 1], cnv[ni].y);
                }
                float m = sc[0];
#pragma unroll
                for (int j = 1; j < 8; j++) m = fminf(m, sc[j]);
                if (m < sm1[s]) {
                    int jm = 7;
#pragma unroll
                    for (int j = 7; j >= 0; j--) if (sc[j] == m) jm = j;
                    float t2 = 3.4e38f;
#pragma unroll
                    for (int j = 0; j < 8; j++) t2 = (j == jm) ? t2 : fminf(t2, sc[j]);
                    uu[s] = fminf(uu[s], fminf(sm1[s], t2));
                    sm1[s] = m;
                    i1[s] = base + (jm >> 1) * 8 + (jm & 1);
                } else {
                    uu[s] = fminf(uu[s], m);
                }
            }
    }

    // ---- row approx min ----
#pragma unroll
    for (int s = 0; s < 4; s++) {
        int row = wm * 32 + (s >> 1) * 16 + (s & 1) * 8 + (lane >> 2);
        atomicMin(&rowmin[row], fp_order(sm1[s]));
    }
    __syncthreads();

    // ---- push candidates: single codes + rare slot fallbacks ----
    const int cbase = wn * 32 + 2 * (lane & 3);
#pragma unroll
    for (int s = 0; s < 4; s++) {
        int row = wm * 32 + (s >> 1) * 16 + (s & 1) * 8 + (lane >> 2);
        float thr = fp_unorder(rowmin[row]) + wrow[row];
        if (sm1[s] <= thr) {
            unsigned slot = atomicAdd(qn, 1u);
            if (slot < QCAP) queue[slot] = ((unsigned)row << 10) | (unsigned)i1[s];
        }
        if (uu[s] <= thr) {
            unsigned slot = atomicAdd(qn, 1u);
            if (slot < QCAP) queue[slot] = 0x80000000u | ((unsigned)row << 7) | (unsigned)cbase;
        }
    }
    __syncthreads();

    // ---- rescue workers ----
    {
        int nq = (int)min(qn[0], (unsigned)QCAP);
        const float* xsf = reinterpret_cast<const float*>(smem + SM_X);
        for (int it = warp; it < nq; it += 16) {
            unsigned item = queue[it];
            if (!(item & 0x80000000u)) {
                // single code: warp-cooperative, 1 float4 per lane
                int row  = (int)(item >> 10);
                int code = (int)(item & 1023u);
                float4 a = reinterpret_cast<const float4*>(xsf + row * DDIM)[lane];
                float4 b = __ldg(&reinterpret_cast<const float4*>(cb + (size_t)code * DDIM)[lane]);
                float d = a.x * b.x + a.y * b.y + a.z * b.z + a.w * b.w;
#pragma unroll
                for (int o = 16; o; o >>= 1) d += __shfl_xor_sync(~0u, d, o);
                if (lane == 0) {
                    float se = fmaf(-2.f, d, cnorm_s[code]);
                    atomicMin(&rowbest[row],
                              ((unsigned long long)fp_order(se) << 32) | (uint32_t)code);
                }
            } else {
                // slot fallback: 64 codes, 2 per lane, per-lane serial dot
                int row = (int)((item >> 7) & 127u);
                int cb0 = (int)(item & 127u);
                const float4* xr = reinterpret_cast<const float4*>(xsf + row * DDIM);
#pragma unroll
                for (int t = 0; t < 2; t++) {
                    int e = lane + t * 32;
                    int code = (e >> 3) * NTILE + ((e >> 1) & 3) * 8 + (e & 1) + cb0;
                    const float4* cr = reinterpret_cast<const float4*>(cb + (size_t)code * DDIM);
                    float d0 = 0.f, d1 = 0.f, d2 = 0.f, d3 = 0.f;
#pragma unroll
                    for (int q = 0; q < 8; q++) {
                        float4 a0 = xr[q * 4 + 0], b0 = __ldg(&cr[q * 4 + 0]);
                        float4 a1 = xr[q * 4 + 1], b1 = __ldg(&cr[q * 4 + 1]);
                        float4 a2 = xr[q * 4 + 2], b2 = __ldg(&cr[q * 4 + 2]);
                        float4 a3 = xr[q * 4 + 3], b3 = __ldg(&cr[q * 4 + 3]);
                        d0 = fmaf(a0.x, b0.x, d0); d0 = fmaf(a0.y, b0.y, d0);
                        d0 = fmaf(a0.z, b0.z, d0); d0 = fmaf(a0.w, b0.w, d0);
                        d1 = fmaf(a1.x, b1.x, d1); d1 = fmaf(a1.y, b1.y, d1);
                        d1 = fmaf(a1.z, b1.z, d1); d1 = fmaf(a1.w, b1.w, d1);
                        d2 = fmaf(a2.x, b2.x, d2); d2 = fmaf(a2.y, b2.y, d2);
                        d2 = fmaf(a2.z, b2.z, d2); d2 = fmaf(a2.w, b2.w, d2);
                        d3 = fmaf(a3.x, b3.x, d3); d3 = fmaf(a3.y, b3.y, d3);
                        d3 = fmaf(a3.z, b3.z, d3); d3 = fmaf(a3.w, b3.w, d3);
                    }
                    float d = (d0 + d1) + (d2 + d3);
                    float se = fmaf(-2.f, d, cnorm_s[code]);
                    atomicMin(&rowbest[row],
                              ((unsigned long long)fp_order(se) << 32) | (uint32_t)code);
                }
            }
        }
    }
    __syncthreads();

    // ---- output: out = x + (q - x), x from SMEM ----
    const float4* cb4 = reinterpret_cast<const float4*>(cb);
    const float4* xs4 = reinterpret_cast<const float4*>(smem + SM_X);
    float4* o4 = reinterpret_cast<float4*>(out);
#pragma unroll
    for (int i = 0; i < 8; i++) {
        int g  = i * NTHREADS + tid;
        int r  = g >> 5, c4 = g & 31;
        int bi = (int)(rowbest[r] & 0xFFFFFFFFu);
        float4 xv = xs4[r * 32 + c4];
        float4 qv = cb4[(size_t)bi * 32 + c4];
        float4 ov;
        ov.x = xv.x + (qv.x - xv.x);
        ov.y = xv.y + (qv.y - xv.y);
        ov.z = xv.z + (qv.z - xv.z);
        ov.w = xv.w + (qv.w - xv.w);
        o4[(size_t)(m0 + r) * 32 + c4] = ov;
    }
}

extern "C" void kernel_launch(void* const* d_in, const int* in_sizes, int n_in,
                              void* d_out, int out_size) {
    const float* x  = (const float*)d_in[0];
    const float* cb = (const float*)d_in[1];
    float* out = (float*)d_out;
    int N = in_sizes[0] / DDIM;     // 32768
    int K = in_sizes[1] / DDIM;     // 1024

    prep_kernel<<<K, DDIM>>>(cb);

    cudaFuncSetAttribute(vq_mma_kernel, cudaFuncAttributeMaxDynamicSharedMemorySize, SMEM_BYTES);
    vq_mma_kernel<<<N / MT, NTHREADS, SMEM_BYTES>>>(x, cb, out);
}